// round 2
// baseline (speedup 1.0000x reference)
#include <cuda_runtime.h>
#include <cstdint>

#define BATCH 1024
#define NCEN  100000
#define DIM   128
#define KNN   200
#define NCLS  100
#define GC    0.005f   // 1/(2*sigma^2), sigma=10

// ---------------- scratch (static device globals; no runtime allocation) ---
__device__ float g_D2[(size_t)BATCH * NCEN];   // 409.6 MB distance matrix
__device__ float g_Ft[DIM * BATCH];            // features transposed [k][b]
__device__ float g_Ct[(size_t)DIM * NCEN];     // centres transposed  [k][n]
__device__ float g_fnorm[BATCH];
__device__ float g_cnorm[NCEN];

// ---------------- packed-f32x2 helpers -------------------------------------
__device__ __forceinline__ unsigned long long bcast2(float x) {
    unsigned long long r;
    asm("mov.b64 %0, {%1, %1};" : "=l"(r) : "r"(__float_as_uint(x)));
    return r;
}
__device__ __forceinline__ void fma2(unsigned long long& c,
                                     unsigned long long a,
                                     unsigned long long b) {
    asm("fma.rn.f32x2 %0, %1, %2, %0;" : "+l"(c) : "l"(a), "l"(b));
}
__device__ __forceinline__ float2 ull2f2(unsigned long long x) {
    float2 r;
    asm("mov.b64 {%0, %1}, %2;" : "=f"(r.x), "=f"(r.y) : "l"(x));
    return r;
}

// ---------------- prep: transpose to k-major + row norms ------------------
__global__ void transpose_kernel(const float* __restrict__ in, int R, int which) {
    __shared__ float tile[32][33];
    float* out = which ? g_Ct : g_Ft;
    int r0 = blockIdx.x * 32, c0 = blockIdx.y * 32;
    int tx = threadIdx.x, ty = threadIdx.y;   // 32 x 8
    #pragma unroll
    for (int i = ty; i < 32; i += 8) {
        int r = r0 + i;
        tile[i][tx] = (r < R) ? in[(size_t)r * DIM + c0 + tx] : 0.f;
    }
    __syncthreads();
    #pragma unroll
    for (int i = ty; i < 32; i += 8) {
        int r = r0 + tx;
        if (r < R) out[(size_t)(c0 + i) * R + r] = tile[tx][i];
    }
}

__global__ void rownorm_kernel(const float* __restrict__ in, int R, int which) {
    float* out = which ? g_cnorm : g_fnorm;
    int w = blockIdx.x * 8 + (threadIdx.x >> 5);
    int lane = threadIdx.x & 31;
    if (w >= R) return;
    float4 v = ((const float4*)(in + (size_t)w * DIM))[lane];
    float s = v.x * v.x + v.y * v.y + v.z * v.z + v.w * v.w;
    #pragma unroll
    for (int o = 16; o; o >>= 1) s += __shfl_xor_sync(0xFFFFFFFFu, s, o);
    if (!lane) out[w] = s;
}

// ---------------- distance GEMM: d2 = fn + cn - 2 * f.c --------------------
#define BM 128
#define BN 128
__global__ __launch_bounds__(256)
void dist_gemm_kernel() {
    extern __shared__ float smbuf[];
    float* As = smbuf;              // [k][m], stride BM
    float* Bs = smbuf + DIM * BM;   // [k][n], stride BN

    int bm = blockIdx.x * BM;   // m fastest -> consecutive CTAs share B tile in L2
    int bn = blockIdx.y * BN;
    int tid = threadIdx.x;

    #pragma unroll
    for (int it = 0; it < 16; it++) {
        int q  = it * 256 + tid;
        int k  = q >> 5;
        int c4 = (q & 31) << 2;
        float4 av = *(const float4*)(g_Ft + (size_t)k * BATCH + bm + c4);
        *(float4*)(As + k * BM + c4) = av;
        int n = bn + c4;
        float4 bv;
        if (n + 3 < NCEN) {
            bv = *(const float4*)(g_Ct + (size_t)k * NCEN + n);
        } else {
            bv.x = (n + 0 < NCEN) ? g_Ct[(size_t)k * NCEN + n + 0] : 0.f;
            bv.y = (n + 1 < NCEN) ? g_Ct[(size_t)k * NCEN + n + 1] : 0.f;
            bv.z = (n + 2 < NCEN) ? g_Ct[(size_t)k * NCEN + n + 2] : 0.f;
            bv.w = (n + 3 < NCEN) ? g_Ct[(size_t)k * NCEN + n + 3] : 0.f;
        }
        *(float4*)(Bs + k * BN + c4) = bv;
    }
    __syncthreads();

    int tx = tid & 15, ty = tid >> 4;
    int m0 = ty * 8, n0 = tx * 8;

    unsigned long long acc[8][4];
    #pragma unroll
    for (int i = 0; i < 8; i++)
        #pragma unroll
        for (int jp = 0; jp < 4; jp++) acc[i][jp] = 0ull;

    #pragma unroll 4
    for (int k = 0; k < DIM; k++) {
        const float* ar = As + k * BM + m0;
        float4 a0 = *(const float4*)(ar);
        float4 a1 = *(const float4*)(ar + 4);
        const ulonglong2* br = (const ulonglong2*)(Bs + k * BN + n0);
        ulonglong2 b01 = br[0];
        ulonglong2 b23 = br[1];
        unsigned long long bb[4] = { b01.x, b01.y, b23.x, b23.y };
        unsigned long long a2[8];
        a2[0] = bcast2(a0.x); a2[1] = bcast2(a0.y);
        a2[2] = bcast2(a0.z); a2[3] = bcast2(a0.w);
        a2[4] = bcast2(a1.x); a2[5] = bcast2(a1.y);
        a2[6] = bcast2(a1.z); a2[7] = bcast2(a1.w);
        #pragma unroll
        for (int i = 0; i < 8; i++)
            #pragma unroll
            for (int jp = 0; jp < 4; jp++)
                fma2(acc[i][jp], a2[i], bb[jp]);
    }

    int mbase = bm + m0;
    float cnv[8];
    #pragma unroll
    for (int j = 0; j < 8; j++) {
        int n = bn + n0 + j;
        cnv[j] = (n < NCEN) ? g_cnorm[n] : 0.f;
    }
    bool full = (bn + BN <= NCEN);
    #pragma unroll
    for (int i = 0; i < 8; i++) {
        float fni = g_fnorm[mbase + i];
        float o[8];
        #pragma unroll
        for (int jp = 0; jp < 4; jp++) {
            float2 d = ull2f2(acc[i][jp]);
            o[2 * jp + 0] = fni + cnv[2 * jp + 0] - 2.f * d.x;
            o[2 * jp + 1] = fni + cnv[2 * jp + 1] - 2.f * d.y;
        }
        float* dst = g_D2 + (size_t)(mbase + i) * NCEN + bn + n0;
        if (full) {
            ((float4*)dst)[0] = make_float4(o[0], o[1], o[2], o[3]);
            ((float4*)dst)[1] = make_float4(o[4], o[5], o[6], o[7]);
        } else {
            #pragma unroll
            for (int j = 0; j < 8; j++)
                if (bn + n0 + j < NCEN) dst[j] = o[j];
        }
    }
}

// ---------------- selection + weights + class log-probs --------------------
#define NBINS    4096
#define CAND_CAP 3072
#define SAMPLE_N 6144
#define TSAMP    25

__device__ __forceinline__ int bucket_of(float v) {
    unsigned int u = __float_as_uint(v);
    if ((int)u <= 0) return 0;                 // <= 0 -> smallest bucket
    int b = (int)(u >> 15) - 32512;            // monotone float-bits bucketing
    return b < 0 ? 0 : (b > NBINS - 1 ? NBINS - 1 : b);
}

__global__ __launch_bounds__(256)
void select_kernel(const float* __restrict__ wgt,
                   const int*   __restrict__ lab32,
                   float*       __restrict__ out) {
    __shared__ unsigned int hist[NBINS];
    __shared__ float        cd2[CAND_CAP];
    __shared__ int          cidx[CAND_CAP];
    __shared__ float        bins[NCLS];
    __shared__ unsigned int scanbuf[256];
    __shared__ int          sT;
    __shared__ unsigned int s_nc;
    __shared__ int          s_is64;
    __shared__ float        s_red[8];

    int b = blockIdx.x, tid = threadIdx.x;
    const float* row = g_D2 + (size_t)b * NCEN;

    for (int i = tid; i < NBINS; i += 256) hist[i] = 0u;
    if (tid < NCLS) bins[tid] = 0.f;
    if (tid == 0) {
        s_nc = 0u;
        // int64 vs int32 label sniff: little-endian int64 labels in [0,100)
        // have all-zero odd 32-bit words. 64 consecutive zero int32 labels
        // has probability ~1e-128.
        int is64 = 1;
        for (int i = 1; i < 128; i += 2)
            if (lab32[i] != 0) { is64 = 0; break; }
        s_is64 = is64;
    }
    __syncthreads();

    // --- sample pass (centres iid => prefix is an unbiased sample)
    for (int s = tid; s < SAMPLE_N; s += 256) {
        atomicAdd(&hist[bucket_of(row[s])], 1u);
    }
    __syncthreads();

    // --- sample-rank-TSAMP bucket via segmented block scan (16 bins/thread)
    unsigned int ls = 0;
    int base = tid * (NBINS / 256);
    #pragma unroll
    for (int j = 0; j < NBINS / 256; j++) ls += hist[base + j];
    scanbuf[tid] = ls;
    __syncthreads();
    for (int off = 1; off < 256; off <<= 1) {
        unsigned int v = (tid >= off) ? scanbuf[tid - off] : 0u;
        __syncthreads();
        scanbuf[tid] += v;
        __syncthreads();
    }
    unsigned int incl = scanbuf[tid], excl = incl - ls;
    if (excl < TSAMP && incl >= TSAMP) {
        unsigned int c = excl;
        for (int j = 0; j < NBINS / 256; j++) {
            c += hist[base + j];
            if (c >= TSAMP) { sT = base + j; break; }
        }
    }
    __syncthreads();

    // --- gather candidates with bucket in (lo, T]; widen T until >= KNN
    int T = sT, lo = -1, nc = 0;
    while (true) {
        for (int i = tid; i < NCEN; i += 256) {
            float v = row[i];
            int bk = bucket_of(v);
            if (bk <= T && bk > lo) {
                unsigned p = atomicAdd(&s_nc, 1u);
                if (p < CAND_CAP) { cd2[p] = v; cidx[p] = i; }
            }
        }
        __syncthreads();
        int ncNow = (int)min(s_nc, (unsigned)CAND_CAP);
        bool done = (ncNow >= KNN) || (T >= NBINS - 1);
        __syncthreads();
        if (done) { nc = ncNow; break; }
        lo = T;
        T  = min(T + 8, NBINS - 1);
    }

    // --- exact rank select (tie-break: smaller index first, matching top_k)
    int is64 = s_is64;
    for (int t = tid; t < nc; t += 256) {
        float dt = cd2[t];
        int   it = cidx[t];
        int r = 0;
        for (int j = 0; j < nc; j++) {
            float dj = cd2[j];
            r += (dj < dt) || (dj == dt && cidx[j] < it);
        }
        if (r < KNN) {
            float w = expf(-dt * GC) * expf(wgt[it]);
            int l = lab32[is64 ? (it << 1) : it];
            atomicAdd(&bins[l], w);
        }
    }
    __syncthreads();

    // --- zero -> 1e-10, sum over classes, log-normalize
    float pv = 0.f;
    if (tid < NCLS) {
        pv = bins[tid];
        if (pv == 0.f) pv = 1e-10f;
    }
    float s = pv;
    #pragma unroll
    for (int o = 16; o; o >>= 1) s += __shfl_xor_sync(0xFFFFFFFFu, s, o);
    if ((tid & 31) == 0 && tid < NCLS) s_red[tid >> 5] = s;
    __syncthreads();
    if (tid == 0) {
        float tot = s_red[0] + s_red[1] + s_red[2] + s_red[3];
        s_red[0] = tot;   // 100 classes span warps 0..3 (tid 0..99)
    }
    __syncthreads();
    if (tid < NCLS) {
        out[(size_t)b * NCLS + tid] = logf(pv / s_red[0]);
    }
}

// ---------------- launch ----------------------------------------------------
extern "C" void kernel_launch(void* const* d_in, const int* in_sizes, int n_in,
                              void* d_out, int out_size) {
    const float* features = (const float*)d_in[0];   // [1024,128]
    const float* centres  = (const float*)d_in[1];   // [100000,128]
    const float* weight   = (const float*)d_in[2];   // [100000]
    const int*   labels   = (const int*)d_in[3];     // int32 or int64 (sniffed)
    float* out = (float*)d_out;

    // prep
    dim3 tb(32, 8);
    transpose_kernel<<<dim3(BATCH / 32, DIM / 32), tb>>>(features, BATCH, 0);
    transpose_kernel<<<dim3((NCEN + 31) / 32, DIM / 32), tb>>>(centres, NCEN, 1);
    rownorm_kernel<<<BATCH / 8, 256>>>(features, BATCH, 0);
    rownorm_kernel<<<(NCEN + 7) / 8, 256>>>(centres, NCEN, 1);

    // distance GEMM (128 KB dynamic smem)
    static const int SMEM = (DIM * BM + DIM * BN) * (int)sizeof(float);
    cudaFuncSetAttribute(dist_gemm_kernel,
                         cudaFuncAttributeMaxDynamicSharedMemorySize, SMEM);
    dim3 grid(BATCH / BM, (NCEN + BN - 1) / BN);
    dist_gemm_kernel<<<grid, 256, SMEM>>>();

    // selection + epilogue
    select_kernel<<<BATCH, 256>>>(weight, labels, out);
}

// round 3
// speedup vs baseline: 1.0074x; 1.0074x over previous
#include <cuda_runtime.h>
#include <cstdint>

#define BATCH 1024
#define NCEN  100000
#define DIM   128
#define KNN   200
#define NCLS  100
#define GC    0.005f   // 1/(2*sigma^2), sigma=10

// ---------------- scratch (static device globals; no runtime allocation) ---
__device__ float g_D2[(size_t)BATCH * NCEN];   // 409.6 MB distance matrix
__device__ float g_Ft[DIM * BATCH];            // features transposed [k][b]
__device__ float g_Ct[(size_t)DIM * NCEN];     // centres transposed  [k][n]
__device__ float g_fnorm[BATCH];
__device__ float g_cnorm[NCEN];

// ---------------- packed-f32x2 helpers -------------------------------------
__device__ __forceinline__ unsigned long long bcast2(float x) {
    unsigned long long r;
    asm("mov.b64 %0, {%1, %1};" : "=l"(r) : "r"(__float_as_uint(x)));
    return r;
}
__device__ __forceinline__ void fma2(unsigned long long& c,
                                     unsigned long long a,
                                     unsigned long long b) {
    asm("fma.rn.f32x2 %0, %1, %2, %0;" : "+l"(c) : "l"(a), "l"(b));
}
__device__ __forceinline__ float2 ull2f2(unsigned long long x) {
    float2 r;
    asm("mov.b64 {%0, %1}, %2;" : "=f"(r.x), "=f"(r.y) : "l"(x));
    return r;
}

// ---------------- prep: transpose to k-major + row norms ------------------
__global__ void transpose_kernel(const float* __restrict__ in, int R, int which) {
    __shared__ float tile[32][33];
    float* out = which ? g_Ct : g_Ft;
    int r0 = blockIdx.x * 32, c0 = blockIdx.y * 32;
    int tx = threadIdx.x, ty = threadIdx.y;   // 32 x 8
    #pragma unroll
    for (int i = ty; i < 32; i += 8) {
        int r = r0 + i;
        tile[i][tx] = (r < R) ? in[(size_t)r * DIM + c0 + tx] : 0.f;
    }
    __syncthreads();
    #pragma unroll
    for (int i = ty; i < 32; i += 8) {
        int r = r0 + tx;
        if (r < R) out[(size_t)(c0 + i) * R + r] = tile[tx][i];
    }
}

__global__ void rownorm_kernel(const float* __restrict__ in, int R, int which) {
    float* out = which ? g_cnorm : g_fnorm;
    int w = blockIdx.x * 8 + (threadIdx.x >> 5);
    int lane = threadIdx.x & 31;
    if (w >= R) return;
    float4 v = ((const float4*)(in + (size_t)w * DIM))[lane];
    float s = v.x * v.x + v.y * v.y + v.z * v.z + v.w * v.w;
    #pragma unroll
    for (int o = 16; o; o >>= 1) s += __shfl_xor_sync(0xFFFFFFFFu, s, o);
    if (!lane) out[w] = s;
}

// ---------------- distance GEMM: d2 = fn + cn - 2 * f.c --------------------
#define BM 128
#define BN 128
__global__ __launch_bounds__(256)
void dist_gemm_kernel() {
    extern __shared__ float smbuf[];
    float* As = smbuf;              // [k][m], stride BM
    float* Bs = smbuf + DIM * BM;   // [k][n], stride BN

    int bm = blockIdx.x * BM;   // m fastest -> consecutive CTAs share B tile in L2
    int bn = blockIdx.y * BN;
    int tid = threadIdx.x;

    #pragma unroll
    for (int it = 0; it < 16; it++) {
        int q  = it * 256 + tid;
        int k  = q >> 5;
        int c4 = (q & 31) << 2;
        float4 av = *(const float4*)(g_Ft + (size_t)k * BATCH + bm + c4);
        *(float4*)(As + k * BM + c4) = av;
        int n = bn + c4;
        float4 bv;
        if (n + 3 < NCEN) {
            bv = *(const float4*)(g_Ct + (size_t)k * NCEN + n);
        } else {
            bv.x = (n + 0 < NCEN) ? g_Ct[(size_t)k * NCEN + n + 0] : 0.f;
            bv.y = (n + 1 < NCEN) ? g_Ct[(size_t)k * NCEN + n + 1] : 0.f;
            bv.z = (n + 2 < NCEN) ? g_Ct[(size_t)k * NCEN + n + 2] : 0.f;
            bv.w = (n + 3 < NCEN) ? g_Ct[(size_t)k * NCEN + n + 3] : 0.f;
        }
        *(float4*)(Bs + k * BN + c4) = bv;
    }
    __syncthreads();

    int tx = tid & 15, ty = tid >> 4;
    int m0 = ty * 8, n0 = tx * 8;

    unsigned long long acc[8][4];
    #pragma unroll
    for (int i = 0; i < 8; i++)
        #pragma unroll
        for (int jp = 0; jp < 4; jp++) acc[i][jp] = 0ull;

    #pragma unroll 4
    for (int k = 0; k < DIM; k++) {
        const float* ar = As + k * BM + m0;
        float4 a0 = *(const float4*)(ar);
        float4 a1 = *(const float4*)(ar + 4);
        const ulonglong2* br = (const ulonglong2*)(Bs + k * BN + n0);
        ulonglong2 b01 = br[0];
        ulonglong2 b23 = br[1];
        unsigned long long bb[4] = { b01.x, b01.y, b23.x, b23.y };
        unsigned long long a2[8];
        a2[0] = bcast2(a0.x); a2[1] = bcast2(a0.y);
        a2[2] = bcast2(a0.z); a2[3] = bcast2(a0.w);
        a2[4] = bcast2(a1.x); a2[5] = bcast2(a1.y);
        a2[6] = bcast2(a1.z); a2[7] = bcast2(a1.w);
        #pragma unroll
        for (int i = 0; i < 8; i++)
            #pragma unroll
            for (int jp = 0; jp < 4; jp++)
                fma2(acc[i][jp], a2[i], bb[jp]);
    }

    int mbase = bm + m0;
    float cnv[8];
    #pragma unroll
    for (int j = 0; j < 8; j++) {
        int n = bn + n0 + j;
        cnv[j] = (n < NCEN) ? g_cnorm[n] : 0.f;
    }
    bool full = (bn + BN <= NCEN);
    #pragma unroll
    for (int i = 0; i < 8; i++) {
        float fni = g_fnorm[mbase + i];
        float o[8];
        #pragma unroll
        for (int jp = 0; jp < 4; jp++) {
            float2 d = ull2f2(acc[i][jp]);
            o[2 * jp + 0] = fni + cnv[2 * jp + 0] - 2.f * d.x;
            o[2 * jp + 1] = fni + cnv[2 * jp + 1] - 2.f * d.y;
        }
        float* dst = g_D2 + (size_t)(mbase + i) * NCEN + bn + n0;
        if (full) {
            ((float4*)dst)[0] = make_float4(o[0], o[1], o[2], o[3]);
            ((float4*)dst)[1] = make_float4(o[4], o[5], o[6], o[7]);
        } else {
            #pragma unroll
            for (int j = 0; j < 8; j++)
                if (bn + n0 + j < NCEN) dst[j] = o[j];
        }
    }
}

// ---------------- selection + weights + class log-probs --------------------
#define NBINS    4096
#define CAND_CAP 3072
#define SAMPLE_N 6144
#define TSAMP    25

__device__ __forceinline__ int bucket_of(float v) {
    unsigned int u = __float_as_uint(v);
    if ((int)u <= 0) return 0;                 // <= 0 -> smallest bucket
    int b = (int)(u >> 15) - 32512;            // monotone float-bits bucketing
    return b < 0 ? 0 : (b > NBINS - 1 ? NBINS - 1 : b);
}

__global__ __launch_bounds__(256)
void select_kernel(const float* __restrict__ wgt,
                   const int*   __restrict__ lab32,
                   float*       __restrict__ out) {
    __shared__ unsigned int hist[NBINS];
    __shared__ float        cd2[CAND_CAP];
    __shared__ int          cidx[CAND_CAP];
    __shared__ float        bins[NCLS];
    __shared__ unsigned int scanbuf[256];
    __shared__ int          sT;
    __shared__ unsigned int s_nc;
    __shared__ int          s_is64;
    __shared__ float        s_red[8];

    int b = blockIdx.x, tid = threadIdx.x;
    const float* row = g_D2 + (size_t)b * NCEN;

    for (int i = tid; i < NBINS; i += 256) hist[i] = 0u;
    if (tid < NCLS) bins[tid] = 0.f;
    if (tid == 0) {
        s_nc = 0u;
        // int64 vs int32 label sniff: little-endian int64 labels in [0,100)
        // have all-zero odd 32-bit words. 64 consecutive zero int32 labels
        // has probability ~1e-128.
        int is64 = 1;
        for (int i = 1; i < 128; i += 2)
            if (lab32[i] != 0) { is64 = 0; break; }
        s_is64 = is64;
    }
    __syncthreads();

    // --- sample pass (centres iid => prefix is an unbiased sample)
    for (int s = tid; s < SAMPLE_N; s += 256) {
        atomicAdd(&hist[bucket_of(row[s])], 1u);
    }
    __syncthreads();

    // --- sample-rank-TSAMP bucket via segmented block scan (16 bins/thread)
    unsigned int ls = 0;
    int base = tid * (NBINS / 256);
    #pragma unroll
    for (int j = 0; j < NBINS / 256; j++) ls += hist[base + j];
    scanbuf[tid] = ls;
    __syncthreads();
    for (int off = 1; off < 256; off <<= 1) {
        unsigned int v = (tid >= off) ? scanbuf[tid - off] : 0u;
        __syncthreads();
        scanbuf[tid] += v;
        __syncthreads();
    }
    unsigned int incl = scanbuf[tid], excl = incl - ls;
    if (excl < TSAMP && incl >= TSAMP) {
        unsigned int c = excl;
        for (int j = 0; j < NBINS / 256; j++) {
            c += hist[base + j];
            if (c >= TSAMP) { sT = base + j; break; }
        }
    }
    __syncthreads();

    // --- gather candidates with bucket in (lo, T]; widen T until >= KNN
    int T = sT, lo = -1, nc = 0;
    while (true) {
        for (int i = tid; i < NCEN; i += 256) {
            float v = row[i];
            int bk = bucket_of(v);
            if (bk <= T && bk > lo) {
                unsigned p = atomicAdd(&s_nc, 1u);
                if (p < CAND_CAP) { cd2[p] = v; cidx[p] = i; }
            }
        }
        __syncthreads();
        int ncNow = (int)min(s_nc, (unsigned)CAND_CAP);
        bool done = (ncNow >= KNN) || (T >= NBINS - 1);
        __syncthreads();
        if (done) { nc = ncNow; break; }
        lo = T;
        T  = min(T + 8, NBINS - 1);
    }

    // --- exact rank select (tie-break: smaller index first, matching top_k)
    int is64 = s_is64;
    for (int t = tid; t < nc; t += 256) {
        float dt = cd2[t];
        int   it = cidx[t];
        int r = 0;
        for (int j = 0; j < nc; j++) {
            float dj = cd2[j];
            r += (dj < dt) || (dj == dt && cidx[j] < it);
        }
        if (r < KNN) {
            float w = expf(-dt * GC) * expf(wgt[it]);
            int l = lab32[is64 ? (it << 1) : it];
            atomicAdd(&bins[l], w);
        }
    }
    __syncthreads();

    // --- zero -> 1e-10, sum over classes, log-normalize
    float pv = 0.f;
    if (tid < NCLS) {
        pv = bins[tid];
        if (pv == 0.f) pv = 1e-10f;
    }
    float s = pv;
    #pragma unroll
    for (int o = 16; o; o >>= 1) s += __shfl_xor_sync(0xFFFFFFFFu, s, o);
    if ((tid & 31) == 0 && tid < NCLS) s_red[tid >> 5] = s;
    __syncthreads();
    if (tid == 0) {
        float tot = s_red[0] + s_red[1] + s_red[2] + s_red[3];
        s_red[0] = tot;   // 100 classes span warps 0..3 (tid 0..99)
    }
    __syncthreads();
    if (tid < NCLS) {
        out[(size_t)b * NCLS + tid] = logf(pv / s_red[0]);
    }
}

// ---------------- launch ----------------------------------------------------
extern "C" void kernel_launch(void* const* d_in, const int* in_sizes, int n_in,
                              void* d_out, int out_size) {
    const float* features = (const float*)d_in[0];   // [1024,128]
    const float* centres  = (const float*)d_in[1];   // [100000,128]
    const float* weight   = (const float*)d_in[2];   // [100000]
    const int*   labels   = (const int*)d_in[3];     // int32 or int64 (sniffed)
    float* out = (float*)d_out;

    // prep
    dim3 tb(32, 8);
    transpose_kernel<<<dim3(BATCH / 32, DIM / 32), tb>>>(features, BATCH, 0);
    transpose_kernel<<<dim3((NCEN + 31) / 32, DIM / 32), tb>>>(centres, NCEN, 1);
    rownorm_kernel<<<BATCH / 8, 256>>>(features, BATCH, 0);
    rownorm_kernel<<<(NCEN + 7) / 8, 256>>>(centres, NCEN, 1);

    // distance GEMM (128 KB dynamic smem)
    static const int SMEM = (DIM * BM + DIM * BN) * (int)sizeof(float);
    cudaFuncSetAttribute(dist_gemm_kernel,
                         cudaFuncAttributeMaxDynamicSharedMemorySize, SMEM);
    dim3 grid(BATCH / BM, (NCEN + BN - 1) / BN);
    dist_gemm_kernel<<<grid, 256, SMEM>>>();

    // selection + epilogue
    select_kernel<<<BATCH, 256>>>(weight, labels, out);
}

// round 6
// speedup vs baseline: 2.2488x; 2.2324x over previous
#include <cuda_runtime.h>
#include <cuda_bf16.h>
#include <cstdint>

#define BATCH 1024
#define NCEN  100000
#define NPAD  100096          // 782 * 128
#define DIM   128
#define KNN   200
#define NCLS  100
#define GC    0.005f

// ---------------- device scratch -------------------------------------------
__device__ float g_D2[(size_t)BATCH * NCEN];          // approx distances
__device__ __nv_bfloat16 g_Ahi[BATCH * DIM];
__device__ __nv_bfloat16 g_Bhi[(size_t)NPAD * DIM];
__device__ float g_fnorm[BATCH];
__device__ float g_cnorm[NCEN];

// ---------------- helpers ---------------------------------------------------
__device__ __forceinline__ uint32_t smem_u32(const void* p) {
    uint32_t a;
    asm("{ .reg .u64 t; cvta.to.shared.u64 t, %1; cvt.u32.u64 %0, t; }"
        : "=r"(a) : "l"(p));
    return a;
}
__device__ __forceinline__ void ldsm4(uint32_t* r, uint32_t addr) {
    asm volatile("ldmatrix.sync.aligned.m8n8.x4.shared.b16 {%0,%1,%2,%3}, [%4];"
                 : "=r"(r[0]), "=r"(r[1]), "=r"(r[2]), "=r"(r[3]) : "r"(addr));
}
__device__ __forceinline__ void mma16816(float* d, const uint32_t* a,
                                         const uint32_t* b) {
    asm volatile(
        "mma.sync.aligned.m16n8k16.row.col.f32.bf16.bf16.f32 "
        "{%0,%1,%2,%3}, {%4,%5,%6,%7}, {%8,%9}, {%0,%1,%2,%3};"
        : "+f"(d[0]), "+f"(d[1]), "+f"(d[2]), "+f"(d[3])
        : "r"(a[0]), "r"(a[1]), "r"(a[2]), "r"(a[3]), "r"(b[0]), "r"(b[1]));
}

// ---------------- prep: norms + hi bf16 -------------------------------------
__global__ void prep_kernel(const float* __restrict__ in, int R, int which) {
    int w = blockIdx.x * 8 + (threadIdx.x >> 5);
    int lane = threadIdx.x & 31;
    if (w >= (which ? NPAD : BATCH)) return;
    __nv_bfloat16* hi = which ? g_Bhi : g_Ahi;
    float4 v = make_float4(0.f, 0.f, 0.f, 0.f);
    if (!which || w < NCEN) v = ((const float4*)(in + (size_t)w * DIM))[lane];
    float s = v.x * v.x + v.y * v.y + v.z * v.z + v.w * v.w;
    #pragma unroll
    for (int o = 16; o; o >>= 1) s += __shfl_xor_sync(0xFFFFFFFFu, s, o);
    if (!lane) {
        if (which) { if (w < NCEN) g_cnorm[w] = s; }
        else g_fnorm[w] = s;
    }
    float f[4] = { v.x, v.y, v.z, v.w };
    ushort4 ph;
    unsigned short* hp = &ph.x;
    #pragma unroll
    for (int i = 0; i < 4; i++) {
        __nv_bfloat16 h = __float2bfloat16(f[i]);
        hp[i] = *(unsigned short*)&h;
    }
    ((ushort4*)(hi + (size_t)w * DIM))[lane] = ph;
}

// ---------------- HMMA approx distance GEMM (single pass, hi only) ----------
// smem: Ahi @ 0, Bhi @ 32768 (64 KB). 128 rows x 256 B, 16B-chunk XOR swizzle.
#define SMT 65536
__device__ __forceinline__ uint32_t swoff(int row, int chunk) {
    return (uint32_t)(row * 256 + ((chunk ^ (row & 7)) << 4));
}

__global__ __launch_bounds__(256, 2)
void dist_mma_kernel() {
    extern __shared__ char smem[];
    uint32_t sb = smem_u32(smem);
    const int tid = threadIdx.x, lane = tid & 31, wid = tid >> 5;
    const int bm = blockIdx.x * 128;   // m fastest: 8 m-CTAs share B tile in L2
    const int bn = blockIdx.y * 128;

    #pragma unroll
    for (int it = 0; it < 8; it++) {
        int q = it * 256 + tid;
        int row = q >> 4, chunk = q & 15;
        uint32_t so = swoff(row, chunk);
        int col = chunk << 3;
        *(uint4*)(smem + 0     + so) = *(const uint4*)(g_Ahi + (size_t)(bm + row) * DIM + col);
        *(uint4*)(smem + 32768 + so) = *(const uint4*)(g_Bhi + (size_t)(bn + row) * DIM + col);
    }
    __syncthreads();

    const int wm = (wid & 1) * 64;
    const int wn = (wid >> 1) * 32;
    const int g  = lane >> 3, l7 = lane & 7;

    const int rowA = wm + ((g & 1) << 3) + l7;
    const int cgA  = g >> 1;
    const int sxA  = rowA & 7;
    const int rowB = wn + ((g >> 1) << 3) + l7;
    const int cgB  = g & 1;
    const int sxB  = rowB & 7;

    float acc[4][4][4];
    #pragma unroll
    for (int mt = 0; mt < 4; mt++)
        #pragma unroll
        for (int nt = 0; nt < 4; nt++)
            #pragma unroll
            for (int r = 0; r < 4; r++) acc[mt][nt][r] = 0.f;

    #pragma unroll
    for (int ks = 0; ks < 8; ks++) {
        int c0 = ks * 2;
        uint32_t afr[4][4], bfr[2][4];
        #pragma unroll
        for (int mt = 0; mt < 4; mt++)
            ldsm4(afr[mt], sb + (uint32_t)((rowA + mt * 16) * 256
                                 + (((c0 + cgA) ^ sxA) << 4)));
        #pragma unroll
        for (int ng = 0; ng < 2; ng++)
            ldsm4(bfr[ng], sb + 32768u + (uint32_t)((rowB + ng * 16) * 256
                                 + (((c0 + cgB) ^ sxB) << 4)));
        #pragma unroll
        for (int mt = 0; mt < 4; mt++)
            #pragma unroll
            for (int nt = 0; nt < 4; nt++)
                mma16816(acc[mt][nt], afr[mt], &bfr[nt >> 1][(nt & 1) * 2]);
    }

    const int qrow = lane >> 2;
    const int qcol = (lane & 3) << 1;
    #pragma unroll
    for (int nt = 0; nt < 4; nt++) {
        int n = bn + wn + nt * 8 + qcol;
        if (n >= NCEN) continue;
        float2 cn = *(const float2*)(g_cnorm + n);
        #pragma unroll
        for (int mt = 0; mt < 4; mt++) {
            int m0 = bm + wm + mt * 16 + qrow;
            float fn0 = g_fnorm[m0];
            float fn1 = g_fnorm[m0 + 8];
            float* d0 = g_D2 + (size_t)m0 * NCEN + n;
            float* d1 = g_D2 + (size_t)(m0 + 8) * NCEN + n;
            *(float2*)d0 = make_float2(fn0 + cn.x - 2.f * acc[mt][nt][0],
                                       fn0 + cn.y - 2.f * acc[mt][nt][1]);
            *(float2*)d1 = make_float2(fn1 + cn.x - 2.f * acc[mt][nt][2],
                                       fn1 + cn.y - 2.f * acc[mt][nt][3]);
        }
    }
}

// ---------------- selection: approx gather -> exact re-rank -----------------
#define NBINS    4096
#define CAND_CAP 3072
#define SAMPLE_N 6144
#define TSAMP    25
#define MINC     256
#define KEEP     240

__device__ __forceinline__ int bucket_of(float v) {
    unsigned int u = __float_as_uint(v);
    if ((int)u <= 0) return 0;
    int b = (int)(u >> 15) - 32512;
    return b < 0 ? 0 : (b > NBINS - 1 ? NBINS - 1 : b);
}

__global__ __launch_bounds__(256)
void select_kernel(const float* __restrict__ features,
                   const float* __restrict__ centres,
                   const float* __restrict__ wgt,
                   const int*   __restrict__ lab32,
                   float*       __restrict__ out) {
    __shared__ unsigned int hist[NBINS];
    __shared__ float        cd2[CAND_CAP];
    __shared__ int          cidx[CAND_CAP];
    __shared__ float        fvec[DIM];
    __shared__ float        kd2[KEEP];
    __shared__ int          kidx[KEEP];
    __shared__ float        bins[NCLS];
    __shared__ unsigned int scanbuf[256];
    __shared__ int          sT;
    __shared__ unsigned int s_nc, s_keep;
    __shared__ int          s_is64;
    __shared__ float        s_red[8];

    int b = blockIdx.x, tid = threadIdx.x;
    int lane = tid & 31, wid = tid >> 5;
    const float* row = g_D2 + (size_t)b * NCEN;

    for (int i = tid; i < NBINS; i += 256) hist[i] = 0u;
    if (tid < NCLS) bins[tid] = 0.f;
    if (tid < DIM / 2)
        *(float2*)(fvec + tid * 2) = *(const float2*)(features + (size_t)b * DIM + tid * 2);
    if (tid == 0) {
        s_nc = 0u; s_keep = 0u;
        int is64 = 1;
        for (int i = 1; i < 128; i += 2)
            if (lab32[i] != 0) { is64 = 0; break; }
        s_is64 = is64;
    }
    __syncthreads();

    // --- sample pass on approx d2
    for (int s = tid; s < SAMPLE_N; s += 256)
        atomicAdd(&hist[bucket_of(row[s])], 1u);
    __syncthreads();

    // --- sample-rank-TSAMP bucket
    unsigned int ls = 0;
    int base = tid * (NBINS / 256);
    #pragma unroll
    for (int j = 0; j < NBINS / 256; j++) ls += hist[base + j];
    scanbuf[tid] = ls;
    __syncthreads();
    for (int off = 1; off < 256; off <<= 1) {
        unsigned int v = (tid >= off) ? scanbuf[tid - off] : 0u;
        __syncthreads();
        scanbuf[tid] += v;
        __syncthreads();
    }
    unsigned int incl = scanbuf[tid], excl = incl - ls;
    if (excl < TSAMP && incl >= TSAMP) {
        unsigned int c = excl;
        for (int j = 0; j < NBINS / 256; j++) {
            c += hist[base + j];
            if (c >= TSAMP) { sT = base + j; break; }
        }
    }
    __syncthreads();

    // --- gather candidates (bucket <= T), widen until >= MINC
    int T = sT, lo = -1, nc = 0;
    while (true) {
        for (int i = tid; i < NCEN; i += 256) {
            float v = row[i];
            int bk = bucket_of(v);
            if (bk <= T && bk > lo) {
                unsigned p = atomicAdd(&s_nc, 1u);
                if (p < CAND_CAP) { cd2[p] = v; cidx[p] = i; }
            }
        }
        __syncthreads();
        int ncNow = (int)min(s_nc, (unsigned)CAND_CAP);
        bool done = (ncNow >= MINC) || (T >= NBINS - 1);
        __syncthreads();
        if (done) { nc = ncNow; break; }
        lo = T;
        T  = min(T + 8, NBINS - 1);
    }

    // --- approx-rank cut to KEEP smallest (margin >> approx noise)
    for (int t = tid; t < nc; t += 256) {
        float dt = cd2[t];
        int   it = cidx[t];
        int r = 0;
        for (int j = 0; j < nc; j++) {
            float dj = cd2[j];
            r += (dj < dt) || (dj == dt && cidx[j] < it);
        }
        if (r < KEEP) {
            unsigned p = atomicAdd(&s_keep, 1u);
            kidx[p] = it;
        }
    }
    __syncthreads();
    int keepN = (int)s_keep;   // == min(nc, KEEP)

    // --- exact fp32 d2 for kept candidates (one warp per candidate)
    float fn = g_fnorm[b];
    for (int c = wid; c < keepN; c += 8) {
        const float4* crow = (const float4*)(centres + (size_t)kidx[c] * DIM);
        float4 cv = crow[lane];
        float4 fv = ((const float4*)fvec)[lane];
        float s1 = fv.x * cv.x + fv.y * cv.y + fv.z * cv.z + fv.w * cv.w;
        float s2 = cv.x * cv.x + cv.y * cv.y + cv.z * cv.z + cv.w * cv.w;
        #pragma unroll
        for (int o = 16; o; o >>= 1) {
            s1 += __shfl_xor_sync(0xFFFFFFFFu, s1, o);
            s2 += __shfl_xor_sync(0xFFFFFFFFu, s2, o);
        }
        if (!lane) kd2[c] = fn + s2 - 2.f * s1;
    }
    __syncthreads();

    // --- exact top-KNN among keepN, weights into class bins
    int is64 = s_is64;
    for (int t = tid; t < keepN; t += 256) {
        float dt = kd2[t];
        int   it = kidx[t];
        int r = 0;
        for (int j = 0; j < keepN; j++) {
            float dj = kd2[j];
            r += (dj < dt) || (dj == dt && kidx[j] < it);
        }
        if (r < KNN) {
            float w = expf(-dt * GC) * expf(wgt[it]);
            int l = lab32[is64 ? (it << 1) : it];
            atomicAdd(&bins[l], w);
        }
    }
    __syncthreads();

    // --- zero -> 1e-10, normalize, log
    float pv = 0.f;
    if (tid < NCLS) {
        pv = bins[tid];
        if (pv == 0.f) pv = 1e-10f;
    }
    float s = pv;
    #pragma unroll
    for (int o = 16; o; o >>= 1) s += __shfl_xor_sync(0xFFFFFFFFu, s, o);
    if ((tid & 31) == 0 && tid < NCLS) s_red[tid >> 5] = s;
    __syncthreads();
    if (tid == 0) s_red[0] = s_red[0] + s_red[1] + s_red[2] + s_red[3];
    __syncthreads();
    if (tid < NCLS)
        out[(size_t)b * NCLS + tid] = logf(pv / s_red[0]);
}

// ---------------- launch ----------------------------------------------------
extern "C" void kernel_launch(void* const* d_in, const int* in_sizes, int n_in,
                              void* d_out, int out_size) {
    const float* features = (const float*)d_in[0];
    const float* centres  = (const float*)d_in[1];
    const float* weight   = (const float*)d_in[2];
    const int*   labels   = (const int*)d_in[3];
    float* out = (float*)d_out;

    prep_kernel<<<BATCH / 8, 256>>>(features, BATCH, 0);
    prep_kernel<<<NPAD / 8, 256>>>(centres, NCEN, 1);

    cudaFuncSetAttribute(dist_mma_kernel,
                         cudaFuncAttributeMaxDynamicSharedMemorySize, SMT);
    dist_mma_kernel<<<dim3(BATCH / 128, NPAD / 128), 256, SMT>>>();

    select_kernel<<<BATCH, 256>>>(features, centres, weight, labels, out);
}

// round 7
// speedup vs baseline: 3.2113x; 1.4280x over previous
#include <cuda_runtime.h>
#include <cuda_bf16.h>
#include <cstdint>

#define BATCH 1024
#define NCEN  100000
#define NPAD  100096          // 782 * 128
#define DIM   128
#define KNN   200
#define NCLS  100
#define GC    0.005f

#define NSAMP 6144            // sample centres (48 n-tiles)
#define TSAMP 60              // sample rank for threshold
#define CAP   3072            // candidate list capacity per query
#define KEEP  240             // approx-rank keep target
#define KMAX  512             // kept-candidate buffer
#define NBINS 4096

// ---------------- device scratch -------------------------------------------
__device__ __nv_bfloat16 g_Ahi[BATCH * DIM];
__device__ __nv_bfloat16 g_Bhi[(size_t)NPAD * DIM];
__device__ float g_fnorm[BATCH];
__device__ float g_cnorm[NCEN];
__device__ float g_D2s[(size_t)BATCH * NSAMP];      // sample approx distances
__device__ float g_edge[BATCH];                      // per-query float threshold
__device__ unsigned int g_cnt[BATCH];
__device__ float g_cd2[(size_t)BATCH * CAP];
__device__ int   g_cidx[(size_t)BATCH * CAP];

// ---------------- helpers ---------------------------------------------------
__device__ __forceinline__ uint32_t smem_u32(const void* p) {
    uint32_t a;
    asm("{ .reg .u64 t; cvta.to.shared.u64 t, %1; cvt.u32.u64 %0, t; }"
        : "=r"(a) : "l"(p));
    return a;
}
__device__ __forceinline__ void ldsm4(uint32_t* r, uint32_t addr) {
    asm volatile("ldmatrix.sync.aligned.m8n8.x4.shared.b16 {%0,%1,%2,%3}, [%4];"
                 : "=r"(r[0]), "=r"(r[1]), "=r"(r[2]), "=r"(r[3]) : "r"(addr));
}
__device__ __forceinline__ void mma16816(float* d, const uint32_t* a,
                                         const uint32_t* b) {
    asm volatile(
        "mma.sync.aligned.m16n8k16.row.col.f32.bf16.bf16.f32 "
        "{%0,%1,%2,%3}, {%4,%5,%6,%7}, {%8,%9}, {%0,%1,%2,%3};"
        : "+f"(d[0]), "+f"(d[1]), "+f"(d[2]), "+f"(d[3])
        : "r"(a[0]), "r"(a[1]), "r"(a[2]), "r"(a[3]), "r"(b[0]), "r"(b[1]));
}
__device__ __forceinline__ int bucket_of(float v) {
    unsigned int u = __float_as_uint(v);
    if ((int)u <= 0) return 0;
    int b = (int)(u >> 15) - 32512;
    return b < 0 ? 0 : (b > NBINS - 1 ? NBINS - 1 : b);
}
// block-wide: smallest bucket T with cum(hist[0..T]) >= rank. 256 threads.
__device__ int bucket_rank(unsigned int* hist, unsigned int* scanbuf,
                           int* sres, int rank, int tid) {
    unsigned int ls = 0;
    int base = tid * (NBINS / 256);
    #pragma unroll
    for (int j = 0; j < NBINS / 256; j++) ls += hist[base + j];
    scanbuf[tid] = ls;
    __syncthreads();
    for (int off = 1; off < 256; off <<= 1) {
        unsigned int v = (tid >= off) ? scanbuf[tid - off] : 0u;
        __syncthreads();
        scanbuf[tid] += v;
        __syncthreads();
    }
    unsigned int incl = scanbuf[tid], excl = incl - ls;
    if (excl < (unsigned)rank && incl >= (unsigned)rank) {
        unsigned int c = excl;
        for (int j = 0; j < NBINS / 256; j++) {
            c += hist[base + j];
            if (c >= (unsigned)rank) { *sres = base + j; break; }
        }
    }
    __syncthreads();
    return *sres;
}

// ---------------- prep: norms + hi bf16 -------------------------------------
__global__ void prep_kernel(const float* __restrict__ in, int which) {
    int w = blockIdx.x * 8 + (threadIdx.x >> 5);
    int lane = threadIdx.x & 31;
    if (w >= (which ? NPAD : BATCH)) return;
    __nv_bfloat16* hi = which ? g_Bhi : g_Ahi;
    float4 v = make_float4(0.f, 0.f, 0.f, 0.f);
    if (!which || w < NCEN) v = ((const float4*)(in + (size_t)w * DIM))[lane];
    float s = v.x * v.x + v.y * v.y + v.z * v.z + v.w * v.w;
    #pragma unroll
    for (int o = 16; o; o >>= 1) s += __shfl_xor_sync(0xFFFFFFFFu, s, o);
    if (!lane) {
        if (which) { if (w < NCEN) g_cnorm[w] = s; }
        else g_fnorm[w] = s;
    }
    float f[4] = { v.x, v.y, v.z, v.w };
    ushort4 ph;
    unsigned short* hp = &ph.x;
    #pragma unroll
    for (int i = 0; i < 4; i++) {
        __nv_bfloat16 h = __float2bfloat16(f[i]);
        hp[i] = *(unsigned short*)&h;
    }
    ((ushort4*)(hi + (size_t)w * DIM))[lane] = ph;
}

__global__ void zero_cnt_kernel() {
    int i = blockIdx.x * 256 + threadIdx.x;
    if (i < BATCH) g_cnt[i] = 0u;
}

// ---------------- shared GEMM mainloop macro body ---------------------------
#define SMT 65536
__device__ __forceinline__ uint32_t swoff(int row, int chunk) {
    return (uint32_t)(row * 256 + ((chunk ^ (row & 7)) << 4));
}

#define GEMM_MAINLOOP(ACC)                                                     \
    const int wm = (wid & 1) * 64;                                             \
    const int wn = (wid >> 1) * 32;                                            \
    const int g  = lane >> 3, l7 = lane & 7;                                   \
    const int rowA = wm + ((g & 1) << 3) + l7;                                 \
    const int cgA  = g >> 1;                                                   \
    const int sxA  = rowA & 7;                                                 \
    const int rowB = wn + ((g >> 1) << 3) + l7;                                \
    const int cgB  = g & 1;                                                    \
    const int sxB  = rowB & 7;                                                 \
    _Pragma("unroll")                                                          \
    for (int it = 0; it < 8; it++) {                                           \
        int q = it * 256 + tid;                                                \
        int row = q >> 4, chunk = q & 15;                                      \
        uint32_t so = swoff(row, chunk);                                       \
        int col = chunk << 3;                                                  \
        *(uint4*)(smem + 0     + so) =                                         \
            *(const uint4*)(g_Ahi + (size_t)(bm + row) * DIM + col);           \
        *(uint4*)(smem + 32768 + so) =                                         \
            *(const uint4*)(g_Bhi + (size_t)(bn + row) * DIM + col);           \
    }                                                                          \
    __syncthreads();                                                           \
    _Pragma("unroll")                                                          \
    for (int ks = 0; ks < 8; ks++) {                                           \
        int c0 = ks * 2;                                                       \
        uint32_t afr[4][4], bfr[2][4];                                         \
        _Pragma("unroll")                                                      \
        for (int mt = 0; mt < 4; mt++)                                         \
            ldsm4(afr[mt], sb + (uint32_t)((rowA + mt * 16) * 256              \
                                 + (((c0 + cgA) ^ sxA) << 4)));                \
        _Pragma("unroll")                                                      \
        for (int ng = 0; ng < 2; ng++)                                         \
            ldsm4(bfr[ng], sb + 32768u + (uint32_t)((rowB + ng * 16) * 256     \
                                 + (((c0 + cgB) ^ sxB) << 4)));                \
        _Pragma("unroll")                                                      \
        for (int mt = 0; mt < 4; mt++)                                         \
            _Pragma("unroll")                                                  \
            for (int nt = 0; nt < 4; nt++)                                     \
                mma16816(ACC[mt][nt], afr[mt], &bfr[nt >> 1][(nt & 1) * 2]);   \
    }

// ---------------- sample GEMM: write approx d2 for first NSAMP centres ------
__global__ __launch_bounds__(256, 2)
void sample_mma_kernel() {
    extern __shared__ char smem[];
    uint32_t sb = smem_u32(smem);
    const int tid = threadIdx.x, lane = tid & 31, wid = tid >> 5;
    const int bm = blockIdx.x * 128;
    const int bn = blockIdx.y * 128;

    float acc[4][4][4];
    #pragma unroll
    for (int mt = 0; mt < 4; mt++)
        #pragma unroll
        for (int nt = 0; nt < 4; nt++)
            #pragma unroll
            for (int r = 0; r < 4; r++) acc[mt][nt][r] = 0.f;

    GEMM_MAINLOOP(acc)

    const int qrow = lane >> 2;
    const int qcol = (lane & 3) << 1;
    #pragma unroll
    for (int mt = 0; mt < 4; mt++) {
        int m0 = bm + wm + mt * 16 + qrow;
        float fn0 = g_fnorm[m0], fn1 = g_fnorm[m0 + 8];
        #pragma unroll
        for (int nt = 0; nt < 4; nt++) {
            int n = bn + wn + nt * 8 + qcol;
            float2 cn = *(const float2*)(g_cnorm + n);
            *(float2*)(g_D2s + (size_t)m0 * NSAMP + n) =
                make_float2(fn0 + cn.x - 2.f * acc[mt][nt][0],
                            fn0 + cn.y - 2.f * acc[mt][nt][1]);
            *(float2*)(g_D2s + (size_t)(m0 + 8) * NSAMP + n) =
                make_float2(fn1 + cn.x - 2.f * acc[mt][nt][2],
                            fn1 + cn.y - 2.f * acc[mt][nt][3]);
        }
    }
}

// ---------------- threshold kernel ------------------------------------------
__global__ __launch_bounds__(256)
void thresh_kernel() {
    __shared__ unsigned int hist[NBINS];
    __shared__ unsigned int scanbuf[256];
    __shared__ int sres;
    int b = blockIdx.x, tid = threadIdx.x;
    for (int i = tid; i < NBINS; i += 256) hist[i] = 0u;
    __syncthreads();
    const float* row = g_D2s + (size_t)b * NSAMP;
    for (int s = tid; s < NSAMP; s += 256)
        atomicAdd(&hist[bucket_of(row[s])], 1u);
    __syncthreads();
    int T = bucket_rank(hist, scanbuf, &sres, TSAMP, tid);
    if (tid == 0)
        g_edge[b] = __uint_as_float((unsigned int)(T + 32513) << 15);
}

// ---------------- main GEMM: filter epilogue --------------------------------
__device__ __forceinline__ void push_cand(int m, float v, int n) {
    unsigned int p = atomicAdd(&g_cnt[m], 1u);
    if (p < CAP) {
        g_cd2[(size_t)m * CAP + p] = v;
        g_cidx[(size_t)m * CAP + p] = n;
    }
}

__global__ __launch_bounds__(256, 2)
void dist_mma_kernel() {
    extern __shared__ char smem[];
    uint32_t sb = smem_u32(smem);
    const int tid = threadIdx.x, lane = tid & 31, wid = tid >> 5;
    const int bm = blockIdx.x * 128;   // m fastest: 8 m-CTAs share B tile in L2
    const int bn = blockIdx.y * 128;

    float acc[4][4][4];
    #pragma unroll
    for (int mt = 0; mt < 4; mt++)
        #pragma unroll
        for (int nt = 0; nt < 4; nt++)
            #pragma unroll
            for (int r = 0; r < 4; r++) acc[mt][nt][r] = 0.f;

    GEMM_MAINLOOP(acc)

    const int qrow = lane >> 2;
    const int qcol = (lane & 3) << 1;
    #pragma unroll
    for (int mt = 0; mt < 4; mt++) {
        int m0 = bm + wm + mt * 16 + qrow;
        float fn0 = g_fnorm[m0], fn1 = g_fnorm[m0 + 8];
        float e0 = g_edge[m0],   e1 = g_edge[m0 + 8];
        #pragma unroll
        for (int nt = 0; nt < 4; nt++) {
            int n = bn + wn + nt * 8 + qcol;      // n even => n+1 < NCEN too
            if (n >= NCEN) continue;
            float2 cn = *(const float2*)(g_cnorm + n);
            float v0 = fn0 + cn.x - 2.f * acc[mt][nt][0];
            float v1 = fn0 + cn.y - 2.f * acc[mt][nt][1];
            float v2 = fn1 + cn.x - 2.f * acc[mt][nt][2];
            float v3 = fn1 + cn.y - 2.f * acc[mt][nt][3];
            if (v0 < e0) push_cand(m0, v0, n);
            if (v1 < e0) push_cand(m0, v1, n + 1);
            if (v2 < e1) push_cand(m0 + 8, v2, n);
            if (v3 < e1) push_cand(m0 + 8, v3, n + 1);
        }
    }
}

// ---------------- selection: candidates -> exact top-200 -> logprobs --------
__global__ __launch_bounds__(256)
void select_kernel(const float* __restrict__ features,
                   const float* __restrict__ centres,
                   const float* __restrict__ wgt,
                   const int*   __restrict__ lab32,
                   float*       __restrict__ out) {
    __shared__ float        scd2[CAP];
    __shared__ int          scidx[CAP];
    __shared__ unsigned int hist[NBINS];
    __shared__ float        kd2[KMAX];
    __shared__ int          kidx[KMAX];
    __shared__ float        fvec[DIM];
    __shared__ float        bins[NCLS];
    __shared__ unsigned int scanbuf[256];
    __shared__ int          sres;
    __shared__ unsigned int s_kn;
    __shared__ int          s_is64;
    __shared__ float        s_red[8];

    int b = blockIdx.x, tid = threadIdx.x;
    int lane = tid & 31, wid = tid >> 5;

    for (int i = tid; i < NBINS; i += 256) hist[i] = 0u;
    if (tid < NCLS) bins[tid] = 0.f;
    if (tid < DIM / 2)
        *(float2*)(fvec + tid * 2) = *(const float2*)(features + (size_t)b * DIM + tid * 2);
    if (tid == 0) {
        s_kn = 0u;
        int is64 = 1;
        for (int i = 1; i < 128; i += 2)
            if (lab32[i] != 0) { is64 = 0; break; }
        s_is64 = is64;
    }
    __syncthreads();

    unsigned int raw = g_cnt[b];
    bool fb = (raw < 320u) || (raw > (unsigned)CAP);
    int kn = 0;

    if (!fb) {
        int nc = (int)raw;
        // load candidates + histogram their approx d2
        for (int i = tid; i < nc; i += 256) {
            float v = g_cd2[(size_t)b * CAP + i];
            scd2[i] = v;
            scidx[i] = g_cidx[(size_t)b * CAP + i];
            atomicAdd(&hist[bucket_of(v)], 1u);
        }
        __syncthreads();
        int Tk = bucket_rank(hist, scanbuf, &sres, KEEP, tid);
        // gather approx-top (bucket <= Tk)
        for (int i = tid; i < nc; i += 256) {
            if (bucket_of(scd2[i]) <= Tk) {
                unsigned int p = atomicAdd(&s_kn, 1u);
                if (p < KMAX) kidx[p] = scidx[i];
            }
        }
        __syncthreads();
        kn = (int)s_kn;
        if (kn > KMAX) fb = true;     // uniform (shared-derived)
        __syncthreads();
        if (!fb) {
            // exact fp32 re-rank distances: one warp per kept candidate
            float fn = g_fnorm[b];
            for (int c = wid; c < kn; c += 8) {
                const float4* crow = (const float4*)(centres + (size_t)kidx[c] * DIM);
                float4 cv = crow[lane];
                float4 fv = ((const float4*)fvec)[lane];
                float s1 = fv.x * cv.x + fv.y * cv.y + fv.z * cv.z + fv.w * cv.w;
                float s2 = cv.x * cv.x + cv.y * cv.y + cv.z * cv.z + cv.w * cv.w;
                #pragma unroll
                for (int o = 16; o; o >>= 1) {
                    s1 += __shfl_xor_sync(0xFFFFFFFFu, s1, o);
                    s2 += __shfl_xor_sync(0xFFFFFFFFu, s2, o);
                }
                if (!lane) kd2[c] = fn + s2 - 2.f * s1;
            }
            __syncthreads();
        }
    }

    if (fb) {
        // deterministic brute-force fallback: exact d2 over all centres
        for (int i = tid; i < NBINS; i += 256) hist[i] = 0u;
        if (tid == 0) s_kn = 0u;
        __syncthreads();
        float fn = g_fnorm[b];
        for (int i = tid; i < NCEN; i += 256) {
            const float4* crow = (const float4*)(centres + (size_t)i * DIM);
            float s1 = 0.f, s2 = 0.f;
            #pragma unroll 8
            for (int j = 0; j < 32; j++) {
                float4 cv = crow[j];
                float4 fv = ((const float4*)fvec)[j];
                s1 += fv.x * cv.x + fv.y * cv.y + fv.z * cv.z + fv.w * cv.w;
                s2 += cv.x * cv.x + cv.y * cv.y + cv.z * cv.z + cv.w * cv.w;
            }
            atomicAdd(&hist[bucket_of(fn + s2 - 2.f * s1)], 1u);
        }
        __syncthreads();
        int T2 = bucket_rank(hist, scanbuf, &sres, KEEP, tid);
        float edge2 = __uint_as_float((unsigned int)(T2 + 32513) << 15);
        for (int i = tid; i < NCEN; i += 256) {
            const float4* crow = (const float4*)(centres + (size_t)i * DIM);
            float s1 = 0.f, s2 = 0.f;
            #pragma unroll 8
            for (int j = 0; j < 32; j++) {
                float4 cv = crow[j];
                float4 fv = ((const float4*)fvec)[j];
                s1 += fv.x * cv.x + fv.y * cv.y + fv.z * cv.z + fv.w * cv.w;
                s2 += cv.x * cv.x + cv.y * cv.y + cv.z * cv.z + cv.w * cv.w;
            }
            float d2 = fn + s2 - 2.f * s1;
            if (d2 < edge2) {
                unsigned int p = atomicAdd(&s_kn, 1u);
                if (p < KMAX) { kd2[p] = d2; kidx[p] = i; }
            }
        }
        __syncthreads();
        kn = (int)min(s_kn, (unsigned)KMAX);
    }

    // --- exact top-KNN among kn (tie-break: smaller index, matching top_k)
    int is64 = s_is64;
    for (int t = tid; t < kn; t += 256) {
        float dt = kd2[t];
        int   it = kidx[t];
        int r = 0;
        for (int j = 0; j < kn; j++) {
            float dj = kd2[j];
            r += (dj < dt) || (dj == dt && kidx[j] < it);
        }
        if (r < KNN) {
            float w = expf(-dt * GC) * expf(wgt[it]);
            int l = lab32[is64 ? (it << 1) : it];
            atomicAdd(&bins[l], w);
        }
    }
    __syncthreads();

    // --- zero -> 1e-10, normalize, log
    float pv = 0.f;
    if (tid < NCLS) {
        pv = bins[tid];
        if (pv == 0.f) pv = 1e-10f;
    }
    float s = pv;
    #pragma unroll
    for (int o = 16; o; o >>= 1) s += __shfl_xor_sync(0xFFFFFFFFu, s, o);
    if ((tid & 31) == 0 && tid < NCLS) s_red[tid >> 5] = s;
    __syncthreads();
    if (tid == 0) s_red[0] = s_red[0] + s_red[1] + s_red[2] + s_red[3];
    __syncthreads();
    if (tid < NCLS)
        out[(size_t)b * NCLS + tid] = logf(pv / s_red[0]);
}

// ---------------- launch ----------------------------------------------------
extern "C" void kernel_launch(void* const* d_in, const int* in_sizes, int n_in,
                              void* d_out, int out_size) {
    const float* features = (const float*)d_in[0];
    const float* centres  = (const float*)d_in[1];
    const float* weight   = (const float*)d_in[2];
    const int*   labels   = (const int*)d_in[3];
    float* out = (float*)d_out;

    prep_kernel<<<BATCH / 8, 256>>>(features, 0);
    prep_kernel<<<NPAD / 8, 256>>>(centres, 1);
    zero_cnt_kernel<<<BATCH / 256, 256>>>();

    cudaFuncSetAttribute(sample_mma_kernel,
                         cudaFuncAttributeMaxDynamicSharedMemorySize, SMT);
    cudaFuncSetAttribute(dist_mma_kernel,
                         cudaFuncAttributeMaxDynamicSharedMemorySize, SMT);

    sample_mma_kernel<<<dim3(BATCH / 128, NSAMP / 128), 256, SMT>>>();
    thresh_kernel<<<BATCH, 256>>>();
    dist_mma_kernel<<<dim3(BATCH / 128, NPAD / 128), 256, SMT>>>();
    select_kernel<<<BATCH, 256>>>(features, centres, weight, labels, out);
}

// round 8
// speedup vs baseline: 4.1250x; 1.2845x over previous
#include <cuda_runtime.h>
#include <cuda_bf16.h>
#include <cstdint>

#define BATCH 1024
#define NCEN  100000
#define NPAD  100096          // 782 * 128
#define DIM   128
#define KNN   200
#define NCLS  100
#define GC    0.005f

#define NSAMP 6144            // sample centres (48 n-tiles)
#define TSAMP 60              // sample rank for threshold
#define CAP   3072            // candidate list capacity per query
#define KEEP  240             // approx-rank keep target
#define KMAX  512             // kept-candidate buffer
#define NBINS 4096

// ---------------- device scratch -------------------------------------------
__device__ __nv_bfloat16 g_Ahi[BATCH * DIM];
__device__ __nv_bfloat16 g_Bhi[(size_t)NPAD * DIM];
__device__ float g_fnorm[BATCH];
__device__ float g_cnorm[NCEN];
__device__ float g_D2s[(size_t)BATCH * NSAMP];
__device__ float g_edge[BATCH];
__device__ unsigned int g_cnt[BATCH];
__device__ float g_cd2[(size_t)BATCH * CAP];
__device__ int   g_cidx[(size_t)BATCH * CAP];

// ---------------- helpers ---------------------------------------------------
__device__ __forceinline__ uint32_t smem_u32(const void* p) {
    uint32_t a;
    asm("{ .reg .u64 t; cvta.to.shared.u64 t, %1; cvt.u32.u64 %0, t; }"
        : "=r"(a) : "l"(p));
    return a;
}
__device__ __forceinline__ void ldsm4(uint32_t* r, uint32_t addr) {
    asm volatile("ldmatrix.sync.aligned.m8n8.x4.shared.b16 {%0,%1,%2,%3}, [%4];"
                 : "=r"(r[0]), "=r"(r[1]), "=r"(r[2]), "=r"(r[3]) : "r"(addr));
}
__device__ __forceinline__ void mma16816(float* d, const uint32_t* a,
                                         const uint32_t* b) {
    asm volatile(
        "mma.sync.aligned.m16n8k16.row.col.f32.bf16.bf16.f32 "
        "{%0,%1,%2,%3}, {%4,%5,%6,%7}, {%8,%9}, {%0,%1,%2,%3};"
        : "+f"(d[0]), "+f"(d[1]), "+f"(d[2]), "+f"(d[3])
        : "r"(a[0]), "r"(a[1]), "r"(a[2]), "r"(a[3]), "r"(b[0]), "r"(b[1]));
}
__device__ __forceinline__ void cp16(uint32_t dst, const void* src) {
    asm volatile("cp.async.cg.shared.global [%0], [%1], 16;"
                 :: "r"(dst), "l"(src) : "memory");
}
__device__ __forceinline__ int bucket_of(float v) {
    unsigned int u = __float_as_uint(v);
    if ((int)u <= 0) return 0;
    int b = (int)(u >> 15) - 32512;
    return b < 0 ? 0 : (b > NBINS - 1 ? NBINS - 1 : b);
}
// block-wide (256 threads): smallest bucket T with cum(hist[0..T]) >= rank
__device__ int bucket_rank(unsigned int* hist, unsigned int* scanbuf,
                           int* sres, int rank, int tid) {
    unsigned int ls = 0;
    int base = tid * (NBINS / 256);
    #pragma unroll
    for (int j = 0; j < NBINS / 256; j++) ls += hist[base + j];
    scanbuf[tid] = ls;
    __syncthreads();
    for (int off = 1; off < 256; off <<= 1) {
        unsigned int v = (tid >= off) ? scanbuf[tid - off] : 0u;
        __syncthreads();
        scanbuf[tid] += v;
        __syncthreads();
    }
    unsigned int incl = scanbuf[tid], excl = incl - ls;
    if (excl < (unsigned)rank && incl >= (unsigned)rank) {
        unsigned int c = excl;
        for (int j = 0; j < NBINS / 256; j++) {
            c += hist[base + j];
            if (c >= (unsigned)rank) { *sres = base + j; break; }
        }
    }
    __syncthreads();
    return *sres;
}

// ---------------- prep: norms + hi bf16 -------------------------------------
__global__ void prep_kernel(const float* __restrict__ in, int which) {
    int w = blockIdx.x * 8 + (threadIdx.x >> 5);
    int lane = threadIdx.x & 31;
    if (w >= (which ? NPAD : BATCH)) return;
    __nv_bfloat16* hi = which ? g_Bhi : g_Ahi;
    float4 v = make_float4(0.f, 0.f, 0.f, 0.f);
    if (!which || w < NCEN) v = ((const float4*)(in + (size_t)w * DIM))[lane];
    float s = v.x * v.x + v.y * v.y + v.z * v.z + v.w * v.w;
    #pragma unroll
    for (int o = 16; o; o >>= 1) s += __shfl_xor_sync(0xFFFFFFFFu, s, o);
    if (!lane) {
        if (which) { if (w < NCEN) g_cnorm[w] = s; }
        else g_fnorm[w] = s;
    }
    float f[4] = { v.x, v.y, v.z, v.w };
    ushort4 ph;
    unsigned short* hp = &ph.x;
    #pragma unroll
    for (int i = 0; i < 4; i++) {
        __nv_bfloat16 h = __float2bfloat16(f[i]);
        hp[i] = *(unsigned short*)&h;
    }
    ((ushort4*)(hi + (size_t)w * DIM))[lane] = ph;
}

__global__ void zero_cnt_kernel() {
    int i = blockIdx.x * 256 + threadIdx.x;
    if (i < BATCH) g_cnt[i] = 0u;
}

// ---------------- GEMM body: 512 thr, 128x128 tile, 32x32 warp tiles --------
#define SMT 65536
__device__ __forceinline__ uint32_t swoff(int row, int chunk) {
    return (uint32_t)(row * 256 + ((chunk ^ (row & 7)) << 4));
}

// after this macro: acc[2][4][4] holds the 32x32 warp tile partial dots
#define GEMM_MAINLOOP(ACC)                                                     \
    const int wm = (wid & 3) * 32;                                             \
    const int wn = (wid >> 2) * 32;                                            \
    const int g  = lane >> 3, l7 = lane & 7;                                   \
    const int rowA = wm + ((g & 1) << 3) + l7;                                 \
    const int cgA  = g >> 1;                                                   \
    const int sxA  = rowA & 7;                                                 \
    const int rowB = wn + ((g >> 1) << 3) + l7;                                \
    const int cgB  = g & 1;                                                    \
    const int sxB  = rowB & 7;                                                 \
    _Pragma("unroll")                                                          \
    for (int it = 0; it < 4; it++) {                                           \
        int q = it * 512 + tid;                                                \
        int row = q >> 4, chunk = q & 15;                                      \
        uint32_t so = swoff(row, chunk);                                       \
        int col = chunk << 3;                                                  \
        cp16(sb + so,          g_Ahi + (size_t)(bm + row) * DIM + col);        \
        cp16(sb + 32768u + so, g_Bhi + (size_t)(bn + row) * DIM + col);        \
    }                                                                          \
    asm volatile("cp.async.commit_group;" ::: "memory");                       \
    asm volatile("cp.async.wait_group 0;" ::: "memory");                       \
    __syncthreads();                                                           \
    _Pragma("unroll")                                                          \
    for (int ks = 0; ks < 8; ks++) {                                           \
        int c0 = ks * 2;                                                       \
        uint32_t afr[2][4], bfr[2][4];                                         \
        _Pragma("unroll")                                                      \
        for (int mt = 0; mt < 2; mt++)                                         \
            ldsm4(afr[mt], sb + (uint32_t)((rowA + mt * 16) * 256              \
                                 + (((c0 + cgA) ^ sxA) << 4)));                \
        _Pragma("unroll")                                                      \
        for (int ng = 0; ng < 2; ng++)                                         \
            ldsm4(bfr[ng], sb + 32768u + (uint32_t)((rowB + ng * 16) * 256     \
                                 + (((c0 + cgB) ^ sxB) << 4)));                \
        _Pragma("unroll")                                                      \
        for (int mt = 0; mt < 2; mt++)                                         \
            _Pragma("unroll")                                                  \
            for (int nt = 0; nt < 4; nt++)                                     \
                mma16816(ACC[mt][nt], afr[mt], &bfr[nt >> 1][(nt & 1) * 2]);   \
    }

// ---------------- sample GEMM ------------------------------------------------
__global__ __launch_bounds__(512, 2)
void sample_mma_kernel() {
    extern __shared__ char smem[];
    uint32_t sb = smem_u32(smem);
    const int tid = threadIdx.x, lane = tid & 31, wid = tid >> 5;
    const int bm = blockIdx.x * 128;
    const int bn = blockIdx.y * 128;

    float acc[2][4][4];
    #pragma unroll
    for (int mt = 0; mt < 2; mt++)
        #pragma unroll
        for (int nt = 0; nt < 4; nt++)
            #pragma unroll
            for (int r = 0; r < 4; r++) acc[mt][nt][r] = 0.f;

    GEMM_MAINLOOP(acc)

    const int qrow = lane >> 2;
    const int qcol = (lane & 3) << 1;
    #pragma unroll
    for (int mt = 0; mt < 2; mt++) {
        int m0 = bm + wm + mt * 16 + qrow;
        float fn0 = g_fnorm[m0], fn1 = g_fnorm[m0 + 8];
        #pragma unroll
        for (int nt = 0; nt < 4; nt++) {
            int n = bn + wn + nt * 8 + qcol;
            float2 cn = *(const float2*)(g_cnorm + n);
            *(float2*)(g_D2s + (size_t)m0 * NSAMP + n) =
                make_float2(fn0 + cn.x - 2.f * acc[mt][nt][0],
                            fn0 + cn.y - 2.f * acc[mt][nt][1]);
            *(float2*)(g_D2s + (size_t)(m0 + 8) * NSAMP + n) =
                make_float2(fn1 + cn.x - 2.f * acc[mt][nt][2],
                            fn1 + cn.y - 2.f * acc[mt][nt][3]);
        }
    }
}

// ---------------- threshold kernel ------------------------------------------
__global__ __launch_bounds__(256)
void thresh_kernel() {
    __shared__ unsigned int hist[NBINS];
    __shared__ unsigned int scanbuf[256];
    __shared__ int sres;
    int b = blockIdx.x, tid = threadIdx.x;
    for (int i = tid; i < NBINS; i += 256) hist[i] = 0u;
    __syncthreads();
    const float* row = g_D2s + (size_t)b * NSAMP;
    for (int s = tid; s < NSAMP; s += 256)
        atomicAdd(&hist[bucket_of(row[s])], 1u);
    __syncthreads();
    int T = bucket_rank(hist, scanbuf, &sres, TSAMP, tid);
    if (tid == 0)
        g_edge[b] = __uint_as_float((unsigned int)(T + 32513) << 15);
}

// ---------------- main GEMM: filter epilogue --------------------------------
__device__ __forceinline__ void push_cand(int m, float v, int n) {
    unsigned int p = atomicAdd(&g_cnt[m], 1u);
    if (p < CAP) {
        g_cd2[(size_t)m * CAP + p] = v;
        g_cidx[(size_t)m * CAP + p] = n;
    }
}

__global__ __launch_bounds__(512, 2)
void dist_mma_kernel() {
    extern __shared__ char smem[];
    uint32_t sb = smem_u32(smem);
    const int tid = threadIdx.x, lane = tid & 31, wid = tid >> 5;
    const int bm = blockIdx.x * 128;   // m fastest: 8 m-CTAs share B tile in L2
    const int bn = blockIdx.y * 128;

    float acc[2][4][4];
    #pragma unroll
    for (int mt = 0; mt < 2; mt++)
        #pragma unroll
        for (int nt = 0; nt < 4; nt++)
            #pragma unroll
            for (int r = 0; r < 4; r++) acc[mt][nt][r] = 0.f;

    GEMM_MAINLOOP(acc)

    const int qrow = lane >> 2;
    const int qcol = (lane & 3) << 1;
    #pragma unroll
    for (int mt = 0; mt < 2; mt++) {
        int m0 = bm + wm + mt * 16 + qrow;
        float fn0 = g_fnorm[m0], fn1 = g_fnorm[m0 + 8];
        float e0 = g_edge[m0],   e1 = g_edge[m0 + 8];
        #pragma unroll
        for (int nt = 0; nt < 4; nt++) {
            int n = bn + wn + nt * 8 + qcol;      // n even => n+1 valid too
            if (n >= NCEN) continue;
            float2 cn = *(const float2*)(g_cnorm + n);
            float v0 = fn0 + cn.x - 2.f * acc[mt][nt][0];
            float v1 = fn0 + cn.y - 2.f * acc[mt][nt][1];
            float v2 = fn1 + cn.x - 2.f * acc[mt][nt][2];
            float v3 = fn1 + cn.y - 2.f * acc[mt][nt][3];
            if (v0 < e0) push_cand(m0, v0, n);
            if (v1 < e0) push_cand(m0, v1, n + 1);
            if (v2 < e1) push_cand(m0 + 8, v2, n);
            if (v3 < e1) push_cand(m0 + 8, v3, n + 1);
        }
    }
}

// ---------------- selection: candidates -> exact top-200 -> logprobs --------
__global__ __launch_bounds__(256)
void select_kernel(const float* __restrict__ features,
                   const float* __restrict__ centres,
                   const float* __restrict__ wgt,
                   const int*   __restrict__ lab32,
                   float*       __restrict__ out) {
    __shared__ float        scd2[CAP];
    __shared__ int          scidx[CAP];
    __shared__ unsigned int hist[NBINS];
    __shared__ float        kd2[KMAX];
    __shared__ int          kidx[KMAX];
    __shared__ float        fvec[DIM];
    __shared__ float        bins[NCLS];
    __shared__ unsigned int scanbuf[256];
    __shared__ int          sres;
    __shared__ unsigned int s_kn;
    __shared__ int          s_is64;
    __shared__ float        s_red[8];

    int b = blockIdx.x, tid = threadIdx.x;
    int lane = tid & 31, wid = tid >> 5;

    for (int i = tid; i < NBINS; i += 256) hist[i] = 0u;
    if (tid < NCLS) bins[tid] = 0.f;
    if (tid < DIM / 2)
        *(float2*)(fvec + tid * 2) = *(const float2*)(features + (size_t)b * DIM + tid * 2);
    if (tid == 0) {
        s_kn = 0u;
        int is64 = 1;
        for (int i = 1; i < 128; i += 2)
            if (lab32[i] != 0) { is64 = 0; break; }
        s_is64 = is64;
    }
    __syncthreads();

    unsigned int raw = g_cnt[b];
    bool fb = (raw < 320u) || (raw > (unsigned)CAP);
    int kn = 0;

    if (!fb) {
        int nc = (int)raw;
        for (int i = tid; i < nc; i += 256) {
            float v = g_cd2[(size_t)b * CAP + i];
            scd2[i] = v;
            scidx[i] = g_cidx[(size_t)b * CAP + i];
            atomicAdd(&hist[bucket_of(v)], 1u);
        }
        __syncthreads();
        int Tk = bucket_rank(hist, scanbuf, &sres, KEEP, tid);
        for (int i = tid; i < nc; i += 256) {
            if (bucket_of(scd2[i]) <= Tk) {
                unsigned int p = atomicAdd(&s_kn, 1u);
                if (p < KMAX) kidx[p] = scidx[i];
            }
        }
        __syncthreads();
        kn = (int)s_kn;
        if (kn > KMAX) fb = true;
        __syncthreads();
        if (!fb) {
            float fn = g_fnorm[b];
            for (int c = wid; c < kn; c += 8) {
                const float4* crow = (const float4*)(centres + (size_t)kidx[c] * DIM);
                float4 cv = crow[lane];
                float4 fv = ((const float4*)fvec)[lane];
                float s1 = fv.x * cv.x + fv.y * cv.y + fv.z * cv.z + fv.w * cv.w;
                float s2 = cv.x * cv.x + cv.y * cv.y + cv.z * cv.z + cv.w * cv.w;
                #pragma unroll
                for (int o = 16; o; o >>= 1) {
                    s1 += __shfl_xor_sync(0xFFFFFFFFu, s1, o);
                    s2 += __shfl_xor_sync(0xFFFFFFFFu, s2, o);
                }
                if (!lane) kd2[c] = fn + s2 - 2.f * s1;
            }
            __syncthreads();
        }
    }

    if (fb) {
        // deterministic exact fallback over all centres
        for (int i = tid; i < NBINS; i += 256) hist[i] = 0u;
        if (tid == 0) s_kn = 0u;
        __syncthreads();
        float fn = g_fnorm[b];
        for (int i = tid; i < NCEN; i += 256) {
            const float4* crow = (const float4*)(centres + (size_t)i * DIM);
            float s1 = 0.f, s2 = 0.f;
            #pragma unroll 8
            for (int j = 0; j < 32; j++) {
                float4 cv = crow[j];
                float4 fv = ((const float4*)fvec)[j];
                s1 += fv.x * cv.x + fv.y * cv.y + fv.z * cv.z + fv.w * cv.w;
                s2 += cv.x * cv.x + cv.y * cv.y + cv.z * cv.z + cv.w * cv.w;
            }
            atomicAdd(&hist[bucket_of(fn + s2 - 2.f * s1)], 1u);
        }
        __syncthreads();
        int T2 = bucket_rank(hist, scanbuf, &sres, KEEP, tid);
        float edge2 = __uint_as_float((unsigned int)(T2 + 32513) << 15);
        for (int i = tid; i < NCEN; i += 256) {
            const float4* crow = (const float4*)(centres + (size_t)i * DIM);
            float s1 = 0.f, s2 = 0.f;
            #pragma unroll 8
            for (int j = 0; j < 32; j++) {
                float4 cv = crow[j];
                float4 fv = ((const float4*)fvec)[j];
                s1 += fv.x * cv.x + fv.y * cv.y + fv.z * cv.z + fv.w * cv.w;
                s2 += cv.x * cv.x + cv.y * cv.y + cv.z * cv.z + cv.w * cv.w;
            }
            float d2 = fn + s2 - 2.f * s1;
            if (d2 < edge2) {
                unsigned int p = atomicAdd(&s_kn, 1u);
                if (p < KMAX) { kd2[p] = d2; kidx[p] = i; }
            }
        }
        __syncthreads();
        kn = (int)min(s_kn, (unsigned)KMAX);
    }

    // --- exact top-KNN among kn (tie-break: smaller index, matching top_k)
    int is64 = s_is64;
    for (int t = tid; t < kn; t += 256) {
        float dt = kd2[t];
        int   it = kidx[t];
        int r = 0;
        for (int j = 0; j < kn; j++) {
            float dj = kd2[j];
            r += (dj < dt) || (dj == dt && kidx[j] < it);
        }
        if (r < KNN) {
            float w = expf(-dt * GC) * expf(wgt[it]);
            int l = lab32[is64 ? (it << 1) : it];
            atomicAdd(&bins[l], w);
        }
    }
    __syncthreads();

    float pv = 0.f;
    if (tid < NCLS) {
        pv = bins[tid];
        if (pv == 0.f) pv = 1e-10f;
    }
    float s = pv;
    #pragma unroll
    for (int o = 16; o; o >>= 1) s += __shfl_xor_sync(0xFFFFFFFFu, s, o);
    if ((tid & 31) == 0 && tid < NCLS) s_red[tid >> 5] = s;
    __syncthreads();
    if (tid == 0) s_red[0] = s_red[0] + s_red[1] + s_red[2] + s_red[3];
    __syncthreads();
    if (tid < NCLS)
        out[(size_t)b * NCLS + tid] = logf(pv / s_red[0]);
}

// ---------------- launch ----------------------------------------------------
extern "C" void kernel_launch(void* const* d_in, const int* in_sizes, int n_in,
                              void* d_out, int out_size) {
    const float* features = (const float*)d_in[0];
    const float* centres  = (const float*)d_in[1];
    const float* weight   = (const float*)d_in[2];
    const int*   labels   = (const int*)d_in[3];
    float* out = (float*)d_out;

    prep_kernel<<<BATCH / 8, 256>>>(features, 0);
    prep_kernel<<<NPAD / 8, 256>>>(centres, 1);
    zero_cnt_kernel<<<BATCH / 256, 256>>>();

    cudaFuncSetAttribute(sample_mma_kernel,
                         cudaFuncAttributeMaxDynamicSharedMemorySize, SMT);
    cudaFuncSetAttribute(dist_mma_kernel,
                         cudaFuncAttributeMaxDynamicSharedMemorySize, SMT);

    sample_mma_kernel<<<dim3(BATCH / 128, NSAMP / 128), 512, SMT>>>();
    thresh_kernel<<<BATCH, 256>>>();
    dist_mma_kernel<<<dim3(BATCH / 128, NPAD / 128), 512, SMT>>>();
    select_kernel<<<BATCH, 256>>>(features, centres, weight, labels, out);
}